// round 1
// baseline (speedup 1.0000x reference)
#include <cuda_runtime.h>
#include <math.h>

// Problem dims
#define B_SZ 4
#define L_SZ 4096
#define D_SZ 1024
#define M_SZ (B_SZ * L_SZ)   // 16384
#define N_SZ (5 * D_SZ)      // 5120
#define K_SZ D_SZ            // 1024

// Scan chunking
#define CHUNKS 32
#define TLEN   128           // CHUNKS*TLEN == L_SZ

// Scratch (device globals: allocation-free per harness rules)
__device__ float  g_Z[(size_t)M_SZ * N_SZ];          // 320 MB: [psi_re|psi_im|phi_re|phi_im|gate]
__device__ float2 g_H[(size_t)M_SZ * D_SZ];          // 128 MB: complex H
__device__ float2 g_E[B_SZ * CHUNKS * D_SZ];         // chunk-local scan ends
__device__ float2 g_Cy[B_SZ * CHUNKS * D_SZ];        // chunk carries

// ---------------------------------------------------------------------------
// TF32 helpers
// ---------------------------------------------------------------------------
__device__ __forceinline__ unsigned cvt_tf32(float x) {
    unsigned u;
    asm("cvt.rna.tf32.f32 %0, %1;" : "=r"(u) : "f"(x));
    return u;
}

__device__ __forceinline__ float4 cvt4_tf32(float4 v) {
    float4 r;
    r.x = __uint_as_float(cvt_tf32(v.x));
    r.y = __uint_as_float(cvt_tf32(v.y));
    r.z = __uint_as_float(cvt_tf32(v.z));
    r.w = __uint_as_float(cvt_tf32(v.w));
    return r;
}

__device__ __forceinline__ void mma_tf32(float c[4], unsigned a0, unsigned a1,
                                         unsigned a2, unsigned a3,
                                         unsigned b0, unsigned b1) {
    asm volatile(
        "mma.sync.aligned.m16n8k8.row.col.f32.tf32.tf32.f32 "
        "{%0,%1,%2,%3}, {%4,%5,%6,%7}, {%8,%9}, {%0,%1,%2,%3};\n"
        : "+f"(c[0]), "+f"(c[1]), "+f"(c[2]), "+f"(c[3])
        : "r"(a0), "r"(a1), "r"(a2), "r"(a3), "r"(b0), "r"(b1));
}

// ---------------------------------------------------------------------------
// GEMM: Z[m, n] = sum_k X[m,k] * W[n,k] + bias[n]
//   128x128 block tile, BK=16, 256 threads, 8 warps (2M x 4N), warp tile 64x32
// ---------------------------------------------------------------------------
#define BM 128
#define BN 128
#define BK 16
#define LDSS 20   // padded smem row stride (floats) -> conflict-free frag loads

__global__ __launch_bounds__(256)
void gemm_kernel(const float* __restrict__ X,
                 const float* __restrict__ Wpsi, const float* __restrict__ bpsi,
                 const float* __restrict__ Wphi, const float* __restrict__ bphi,
                 const float* __restrict__ Wgate, const float* __restrict__ bgate) {
    __shared__ float As[BM * LDSS];
    __shared__ float Bs[BN * LDSS];

    const int tid = threadIdx.x;
    const int bn = blockIdx.x, bm = blockIdx.y;
    const int n0 = bn * BN;

    // Segment select (tiles never straddle: 2048/4096 divisible by 128)
    const float* Wt;
    const float* bt;
    int segOff;
    if (n0 < 2048)      { Wt = Wpsi;  bt = bpsi;  segOff = 0;    }
    else if (n0 < 4096) { Wt = Wphi;  bt = bphi;  segOff = 2048; }
    else                { Wt = Wgate; bt = bgate; segOff = 4096; }

    const int loadRow = tid >> 1;        // 0..127
    const int loadK   = (tid & 1) * 8;   // 0 or 8

    const float* aPtr = X  + (size_t)(bm * BM + loadRow) * K_SZ + loadK;
    const float* bPtr = Wt + (size_t)(n0 - segOff + loadRow) * K_SZ + loadK;

    const int lane = tid & 31, warp = tid >> 5;
    const int warpM = warp & 1, warpN = warp >> 1;
    const int gid = lane >> 2, tig = lane & 3;

    float acc[4][4][4];
#pragma unroll
    for (int i = 0; i < 4; i++)
#pragma unroll
        for (int j = 0; j < 4; j++)
#pragma unroll
            for (int k = 0; k < 4; k++) acc[i][j][k] = 0.f;

    // Prologue: first global tile into regs
    float4 ra0 = *(const float4*)(aPtr);
    float4 ra1 = *(const float4*)(aPtr + 4);
    float4 rb0 = *(const float4*)(bPtr);
    float4 rb1 = *(const float4*)(bPtr + 4);

    const int KT = K_SZ / BK;  // 64
    for (int kt = 0; kt < KT; kt++) {
        // Stage regs -> smem (with TF32 rounding)
        float* as = &As[loadRow * LDSS + loadK];
        float* bs = &Bs[loadRow * LDSS + loadK];
        *(float4*)(as)     = cvt4_tf32(ra0);
        *(float4*)(as + 4) = cvt4_tf32(ra1);
        *(float4*)(bs)     = cvt4_tf32(rb0);
        *(float4*)(bs + 4) = cvt4_tf32(rb1);
        __syncthreads();

        // Prefetch next tile
        if (kt + 1 < KT) {
            aPtr += BK; bPtr += BK;
            ra0 = *(const float4*)(aPtr);
            ra1 = *(const float4*)(aPtr + 4);
            rb0 = *(const float4*)(bPtr);
            rb1 = *(const float4*)(bPtr + 4);
        }

        // Two k=8 MMA steps
#pragma unroll
        for (int ks = 0; ks < 2; ks++) {
            const int kb = ks * 8;
            unsigned af[4][4], bf[4][2];
#pragma unroll
            for (int mi = 0; mi < 4; mi++) {
                const int r = warpM * 64 + mi * 16;
                af[mi][0] = __float_as_uint(As[(r + gid)     * LDSS + kb + tig]);
                af[mi][1] = __float_as_uint(As[(r + gid + 8) * LDSS + kb + tig]);
                af[mi][2] = __float_as_uint(As[(r + gid)     * LDSS + kb + tig + 4]);
                af[mi][3] = __float_as_uint(As[(r + gid + 8) * LDSS + kb + tig + 4]);
            }
#pragma unroll
            for (int ni = 0; ni < 4; ni++) {
                const int cN = warpN * 32 + ni * 8;
                bf[ni][0] = __float_as_uint(Bs[(cN + gid) * LDSS + kb + tig]);
                bf[ni][1] = __float_as_uint(Bs[(cN + gid) * LDSS + kb + tig + 4]);
            }
#pragma unroll
            for (int mi = 0; mi < 4; mi++)
#pragma unroll
                for (int ni = 0; ni < 4; ni++)
                    mma_tf32(acc[mi][ni], af[mi][0], af[mi][1], af[mi][2], af[mi][3],
                             bf[ni][0], bf[ni][1]);
        }
        __syncthreads();
    }

    // Epilogue: bias + store
#pragma unroll
    for (int mi = 0; mi < 4; mi++) {
#pragma unroll
        for (int ni = 0; ni < 4; ni++) {
            const int row = bm * BM + warpM * 64 + mi * 16 + gid;
            const int col = n0 + warpN * 32 + ni * 8 + tig * 2;
            const float bv0 = bt[col - segOff];
            const float bv1 = bt[col + 1 - segOff];
            float2 v0 = make_float2(acc[mi][ni][0] + bv0, acc[mi][ni][1] + bv1);
            float2 v1 = make_float2(acc[mi][ni][2] + bv0, acc[mi][ni][3] + bv1);
            *(float2*)&g_Z[(size_t)row * N_SZ + col]       = v0;
            *(float2*)&g_Z[(size_t)(row + 8) * N_SZ + col] = v1;
        }
    }
}

// ---------------------------------------------------------------------------
// Scan: H[l] = r * H[l-1] + U[l],  U = sigmoid(gate) * (psi_re + i*psi_im)
//   r_d = exp(lambda_d * dt),  lambda_d = -exp(log_gamma_d) + i*omega_d
// ---------------------------------------------------------------------------
__device__ __forceinline__ void load_u(const float* Zrow, float& ure, float& uim) {
    const float pre = Zrow[0];
    const float pim = Zrow[1024];
    const float gt  = Zrow[4096];
    const float s = 1.f / (1.f + __expf(-gt) * 0.f + expf(-gt));  // exact expf
    ure = s * pre;
    uim = s * pim;
}

__global__ void scan_pass1(const float* __restrict__ omega,
                           const float* __restrict__ lg,
                           const float* __restrict__ dtp) {
    const int d = blockIdx.x * blockDim.x + threadIdx.x;   // 0..1023
    const int c = blockIdx.y;
    const int b = blockIdx.z;
    const float dt = fabsf(*dtp);
    const float decay = expf(-expf(lg[d]) * dt);
    const float ang = omega[d] * dt;
    const float rre = decay * cosf(ang), rim = decay * sinf(ang);

    float hre = 0.f, him = 0.f;
    const float* Zrow = g_Z + (size_t)(b * L_SZ + c * TLEN) * N_SZ + d;
    for (int i = 0; i < TLEN; i++) {
        float ure, uim;
        load_u(Zrow, ure, uim);
        const float nre = rre * hre - rim * him + ure;
        him = rre * him + rim * hre + uim;
        hre = nre;
        Zrow += N_SZ;
    }
    g_E[(b * CHUNKS + c) * D_SZ + d] = make_float2(hre, him);
}

__global__ void scan_pass2(const float* __restrict__ omega,
                           const float* __restrict__ lg,
                           const float* __restrict__ dtp) {
    const int d = blockIdx.x * blockDim.x + threadIdx.x;
    const int b = blockIdx.y;
    const float dt = fabsf(*dtp);
    // r^TLEN = exp(lambda * dt * TLEN)
    const float decayT = expf(-expf(lg[d]) * dt * (float)TLEN);
    const float angT = omega[d] * dt * (float)TLEN;
    const float rTre = decayT * cosf(angT), rTim = decayT * sinf(angT);

    float cre = 0.f, cim = 0.f;
    for (int c = 0; c < CHUNKS; c++) {
        g_Cy[(b * CHUNKS + c) * D_SZ + d] = make_float2(cre, cim);
        const float2 e = g_E[(b * CHUNKS + c) * D_SZ + d];
        const float nre = e.x + rTre * cre - rTim * cim;
        cim = e.y + rTre * cim + rTim * cre;
        cre = nre;
    }
}

__global__ void scan_pass3(const float* __restrict__ omega,
                           const float* __restrict__ lg,
                           const float* __restrict__ dtp) {
    const int d = blockIdx.x * blockDim.x + threadIdx.x;
    const int c = blockIdx.y;
    const int b = blockIdx.z;
    const float dt = fabsf(*dtp);
    const float decay = expf(-expf(lg[d]) * dt);
    const float ang = omega[d] * dt;
    const float rre = decay * cosf(ang), rim = decay * sinf(ang);

    const float2 cy = g_Cy[(b * CHUNKS + c) * D_SZ + d];
    float hre = cy.x, him = cy.y;
    const float* Zrow = g_Z + (size_t)(b * L_SZ + c * TLEN) * N_SZ + d;
    float2* Hrow = g_H + (size_t)(b * L_SZ + c * TLEN) * D_SZ + d;
    for (int i = 0; i < TLEN; i++) {
        float ure, uim;
        load_u(Zrow, ure, uim);
        const float nre = rre * hre - rim * him + ure;
        him = rre * him + rim * hre + uim;
        hre = nre;
        *Hrow = make_float2(hre, him);
        Zrow += N_SZ;
        Hrow += D_SZ;
    }
}

// ---------------------------------------------------------------------------
// Projection + output:
//   z = (H - mean) / (sqrt(var) + 1e-6) per row (re/im separately, biased var)
//   out = z_re * phi_re + z_im * phi_im
// ---------------------------------------------------------------------------
__global__ __launch_bounds__(256)
void proj_kernel(float* __restrict__ out) {
    const int m = blockIdx.x;
    const int tid = threadIdx.x;
    const int lane = tid & 31, warp = tid >> 5;

    __shared__ float2 sh[D_SZ];
    __shared__ float redA[8], redB[8];

    float sre = 0.f, sim = 0.f;
    for (int i = tid; i < D_SZ; i += 256) {
        const float2 h = g_H[(size_t)m * D_SZ + i];
        sh[i] = h;
        sre += h.x;
        sim += h.y;
    }
#pragma unroll
    for (int off = 16; off > 0; off >>= 1) {
        sre += __shfl_down_sync(0xFFFFFFFFu, sre, off);
        sim += __shfl_down_sync(0xFFFFFFFFu, sim, off);
    }
    if (lane == 0) { redA[warp] = sre; redB[warp] = sim; }
    __syncthreads();
    float mre = 0.f, mim = 0.f;
#pragma unroll
    for (int w = 0; w < 8; w++) { mre += redA[w]; mim += redB[w]; }
    mre *= (1.f / D_SZ);
    mim *= (1.f / D_SZ);
    __syncthreads();

    float vre = 0.f, vim = 0.f;
    for (int i = tid; i < D_SZ; i += 256) {
        const float2 h = sh[i];
        const float dr = h.x - mre, di = h.y - mim;
        vre += dr * dr;
        vim += di * di;
    }
#pragma unroll
    for (int off = 16; off > 0; off >>= 1) {
        vre += __shfl_down_sync(0xFFFFFFFFu, vre, off);
        vim += __shfl_down_sync(0xFFFFFFFFu, vim, off);
    }
    if (lane == 0) { redA[warp] = vre; redB[warp] = vim; }
    __syncthreads();
    float tvre = 0.f, tvim = 0.f;
#pragma unroll
    for (int w = 0; w < 8; w++) { tvre += redA[w]; tvim += redB[w]; }
    const float invre = 1.f / (sqrtf(tvre * (1.f / D_SZ)) + 1e-6f);
    const float invim = 1.f / (sqrtf(tvim * (1.f / D_SZ)) + 1e-6f);

    for (int i = tid; i < D_SZ; i += 256) {
        const float2 h = sh[i];
        const float zre = (h.x - mre) * invre;
        const float zim = (h.y - mim) * invim;
        const float pre = g_Z[(size_t)m * N_SZ + 2048 + i];
        const float pim = g_Z[(size_t)m * N_SZ + 3072 + i];
        out[(size_t)m * D_SZ + i] = zre * pre + zim * pim;
    }
}

// ---------------------------------------------------------------------------
extern "C" void kernel_launch(void* const* d_in, const int* in_sizes, int n_in,
                              void* d_out, int out_size) {
    const float* x     = (const float*)d_in[0];
    const float* omega = (const float*)d_in[1];
    const float* lg    = (const float*)d_in[2];
    const float* dt    = (const float*)d_in[3];
    const float* Wpsi  = (const float*)d_in[4];
    const float* bpsi  = (const float*)d_in[5];
    const float* Wphi  = (const float*)d_in[6];
    const float* bphi  = (const float*)d_in[7];
    const float* Wgate = (const float*)d_in[8];
    const float* bgate = (const float*)d_in[9];
    float* out = (float*)d_out;

    gemm_kernel<<<dim3(N_SZ / BN, M_SZ / BM), 256>>>(x, Wpsi, bpsi, Wphi, bphi,
                                                     Wgate, bgate);
    scan_pass1<<<dim3(D_SZ / 256, CHUNKS, B_SZ), 256>>>(omega, lg, dt);
    scan_pass2<<<dim3(D_SZ / 256, B_SZ), 256>>>(omega, lg, dt);
    scan_pass3<<<dim3(D_SZ / 256, CHUNKS, B_SZ), 256>>>(omega, lg, dt);
    proj_kernel<<<M_SZ, 256>>>(out);
}

// round 5
// speedup vs baseline: 1.8612x; 1.8612x over previous
#include <cuda_runtime.h>
#include <math.h>
#include <stdint.h>

// Problem dims
#define B_SZ 4
#define L_SZ 4096
#define D_SZ 1024
#define M_SZ (B_SZ * L_SZ)   // 16384
#define N_SZ (5 * D_SZ)      // 5120
#define K_SZ D_SZ            // 1024

// Scan chunking
#define CHUNKS 32
#define TLEN   128

// Scratch (device globals)
__device__ float  g_Z[(size_t)M_SZ * N_SZ];     // [psi_re|psi_im|phi_re|phi_im|gate]
__device__ float2 g_E[B_SZ * CHUNKS * D_SZ];
__device__ float2 g_Cy[B_SZ * CHUNKS * D_SZ];
__device__ float  g_Xa[(size_t)M_SZ * K_SZ];    // fragment-major tf32 X
__device__ float  g_Wc[(size_t)N_SZ * K_SZ];    // fragment-major tf32 weights
__device__ float  g_bias[N_SZ];

// ---------------------------------------------------------------------------
// helpers
// ---------------------------------------------------------------------------
__device__ __forceinline__ unsigned cvt_tf32(float x) {
    unsigned u;
    asm("cvt.rna.tf32.f32 %0, %1;" : "=r"(u) : "f"(x));
    return u;
}
__device__ __forceinline__ uint32_t smem_u32(const void* p) {
    uint32_t a;
    asm("{ .reg .u64 t; cvta.to.shared.u64 t, %1; cvt.u32.u64 %0, t; }"
        : "=r"(a) : "l"(p));
    return a;
}
__device__ __forceinline__ void mma_tf32(float c[4], unsigned a0, unsigned a1,
                                         unsigned a2, unsigned a3,
                                         unsigned b0, unsigned b1) {
    asm volatile(
        "mma.sync.aligned.m16n8k8.row.col.f32.tf32.tf32.f32 "
        "{%0,%1,%2,%3}, {%4,%5,%6,%7}, {%8,%9}, {%0,%1,%2,%3};\n"
        : "+f"(c[0]), "+f"(c[1]), "+f"(c[2]), "+f"(c[3])
        : "r"(a0), "r"(a1), "r"(a2), "r"(a3), "r"(b0), "r"(b1));
}
__device__ __forceinline__ void cp_async16(uint32_t smem, const void* gptr) {
    asm volatile("cp.async.cg.shared.global [%0], [%1], 16;"
                 :: "r"(smem), "l"(gptr) : "memory");
}

// ---------------------------------------------------------------------------
// Fragment-major pre-convert passes (tf32 RNA rounding baked in)
//
// A layout: unit u = (((m_blk*32 + kt)*8 + mi)*4 + kb)*32 + lane, float4 per
// unit: { X[m,k], X[m+8,k], X[m,k+4], X[m+8,k+4] },
//   m = m_blk*128 + mi*16 + (lane>>2), k = kt*32 + kb*8 + (lane&3)
// ---------------------------------------------------------------------------
__global__ void cvtA_kernel(const float* __restrict__ x) {
    const unsigned u = blockIdx.x * 256 + threadIdx.x;   // < 4194304
    const int lane = u & 31, gid = lane >> 2, tig = lane & 3;
    const int kb = (u >> 5) & 3, mi = (u >> 7) & 7;
    const int kt = (u >> 10) & 31, mb = u >> 15;
    const int m = mb * 128 + mi * 16 + gid;
    const int k = kt * 32 + kb * 8 + tig;
    const float* xp = x + (size_t)m * K_SZ + k;
    uint4 v;
    v.x = cvt_tf32(xp[0]);
    v.y = cvt_tf32(xp[8 * K_SZ]);
    v.z = cvt_tf32(xp[4]);
    v.w = cvt_tf32(xp[8 * K_SZ + 4]);
    ((uint4*)g_Xa)[u] = v;
}

// B layout: unit u = (((n_blk*32 + kt)*16 + ni)*2 + ks2)*32 + lane, float4:
//   { W[n,k0], W[n,k0+4], W[n,k0+8], W[n,k0+12] },
//   n = n_blk*128 + ni*8 + (lane>>2), k0 = kt*32 + ks2*16 + (lane&3)
__global__ void cvtB_kernel(const float* __restrict__ Wpsi,
                            const float* __restrict__ Wphi,
                            const float* __restrict__ Wgate) {
    const unsigned u = blockIdx.x * 256 + threadIdx.x;   // < 1310720
    const int lane = u & 31, gid = lane >> 2, tig = lane & 3;
    const int ks2 = (u >> 5) & 1, ni = (u >> 6) & 15;
    const int kt = (u >> 10) & 31, nb = u >> 15;
    const int n = nb * 128 + ni * 8 + gid;
    const int k0 = kt * 32 + ks2 * 16 + tig;
    const float* Wp;
    int n_loc;
    if (n < 2048)      { Wp = Wpsi;  n_loc = n; }
    else if (n < 4096) { Wp = Wphi;  n_loc = n - 2048; }
    else               { Wp = Wgate; n_loc = n - 4096; }
    const float* wp = Wp + (size_t)n_loc * K_SZ + k0;
    uint4 v;
    v.x = cvt_tf32(wp[0]);
    v.y = cvt_tf32(wp[4]);
    v.z = cvt_tf32(wp[8]);
    v.w = cvt_tf32(wp[12]);
    ((uint4*)g_Wc)[u] = v;
}

__global__ void biascat_kernel(const float* __restrict__ bp,
                               const float* __restrict__ bh,
                               const float* __restrict__ bg) {
    int i = blockIdx.x * 256 + threadIdx.x;
    float v = (i < 2048) ? bp[i] : ((i < 4096) ? bh[i - 2048] : bg[i - 4096]);
    g_bias[i] = v;
}

// ---------------------------------------------------------------------------
// TF32 mma.sync GEMM, fragment-major smem, 3-stage cp.async pipeline
//   CTA tile 128x128, BK=32, 256 threads (8 warps: 2M x 4N), warp tile 64x32
//   Stage = A 16KB + B 16KB (contiguous block copies, no swizzle/pad)
// ---------------------------------------------------------------------------
#define STAGES 3
#define NT 32                        // K tiles of 32
#define STAGE_U4 2048                // uint4 per stage
#define GEMM_SMEM (STAGES * 32768 + 512)

__global__ __launch_bounds__(256, 2)
void gemm_tc(const float* __restrict__ Xp, const float* __restrict__ Wp,
             const float* __restrict__ bias) {
    extern __shared__ __align__(16) uint4 smem4[];
    float* bsm = (float*)(smem4 + STAGES * STAGE_U4);

    const int tid = threadIdx.x;
    const int lane = tid & 31, warp = tid >> 5;
    const int warpM = warp & 1, warpN = warp >> 1;
    const int gid = lane >> 2, tig = lane & 3;
    const int bn = blockIdx.x, bm = blockIdx.y;

    if (tid < 128) bsm[tid] = bias[bn * 128 + tid];

    const uint4* Ag = (const uint4*)Xp + (size_t)bm * NT * 1024;
    const uint4* Bg = (const uint4*)Wp + (size_t)bn * NT * 1024;
    const uint32_t sb = smem_u32(smem4);

    // prologue: tiles 0,1 into stages 0,1
#pragma unroll
    for (int s = 0; s < STAGES - 1; s++) {
        const uint32_t base = sb + s * 32768;
#pragma unroll
        for (int i = 0; i < 4; i++) {
            const int c = i * 256 + tid;
            cp_async16(base + c * 16, Ag + (size_t)s * 1024 + c);
            cp_async16(base + 16384 + c * 16, Bg + (size_t)s * 1024 + c);
        }
        asm volatile("cp.async.commit_group;" ::: "memory");
    }

    float acc[4][4][4];
#pragma unroll
    for (int i = 0; i < 4; i++)
#pragma unroll
        for (int j = 0; j < 4; j++)
#pragma unroll
            for (int k = 0; k < 4; k++) acc[i][j][k] = 0.f;

    for (int t = 0; t < NT; t++) {
        if (t + STAGES - 1 < NT) {
            const int tt = t + STAGES - 1;
            const uint32_t base = sb + (tt % STAGES) * 32768;
#pragma unroll
            for (int i = 0; i < 4; i++) {
                const int c = i * 256 + tid;
                cp_async16(base + c * 16, Ag + (size_t)tt * 1024 + c);
                cp_async16(base + 16384 + c * 16, Bg + (size_t)tt * 1024 + c);
            }
        }
        asm volatile("cp.async.commit_group;" ::: "memory");
        asm volatile("cp.async.wait_group %0;" :: "n"(STAGES - 1) : "memory");
        __syncthreads();

        const uint4* As = smem4 + (t % STAGES) * STAGE_U4;
        const uint4* Bs = As + 1024;

#pragma unroll
        for (int ks2 = 0; ks2 < 2; ks2++) {
            uint4 bq[4];
#pragma unroll
            for (int ni = 0; ni < 4; ni++)
                bq[ni] = Bs[((warpN * 4 + ni) * 2 + ks2) * 32 + lane];
#pragma unroll
            for (int half = 0; half < 2; half++) {
                const int k8 = ks2 * 2 + half;
                uint4 aq[4];
#pragma unroll
                for (int mi = 0; mi < 4; mi++)
                    aq[mi] = As[((warpM * 4 + mi) * 4 + k8) * 32 + lane];
#pragma unroll
                for (int mi = 0; mi < 4; mi++)
#pragma unroll
                    for (int ni = 0; ni < 4; ni++)
                        mma_tf32(acc[mi][ni], aq[mi].x, aq[mi].y, aq[mi].z,
                                 aq[mi].w,
                                 half ? bq[ni].z : bq[ni].x,
                                 half ? bq[ni].w : bq[ni].y);
            }
        }
        __syncthreads();
    }

    // Epilogue: bias + store
    const int m0 = bm * 128, n0 = bn * 128;
#pragma unroll
    for (int mi = 0; mi < 4; mi++) {
#pragma unroll
        for (int ni = 0; ni < 4; ni++) {
            const int row = m0 + warpM * 64 + mi * 16 + gid;
            const int colL = warpN * 32 + ni * 8 + tig * 2;
            const float bv0 = bsm[colL];
            const float bv1 = bsm[colL + 1];
            float2 v0 = make_float2(acc[mi][ni][0] + bv0, acc[mi][ni][1] + bv1);
            float2 v1 = make_float2(acc[mi][ni][2] + bv0, acc[mi][ni][3] + bv1);
            *(float2*)&g_Z[(size_t)row * N_SZ + n0 + colL]       = v0;
            *(float2*)&g_Z[(size_t)(row + 8) * N_SZ + n0 + colL] = v1;
        }
    }
}

// ---------------------------------------------------------------------------
// Scan pass1: per-chunk local recurrence ends (1024-thread blocks, pipelined)
// ---------------------------------------------------------------------------
__global__ __launch_bounds__(1024)
void scan_pass1(const float* __restrict__ omega, const float* __restrict__ lg,
                const float* __restrict__ dtp) {
    const int d = threadIdx.x;
    const int c = blockIdx.x;
    const int b = blockIdx.y;
    const float dt = fabsf(*dtp);
    const float decay = expf(-expf(lg[d]) * dt);
    const float ang = omega[d] * dt;
    const float rre = decay * cosf(ang), rim = decay * sinf(ang);

    const float* Zrow = g_Z + (size_t)(b * L_SZ + c * TLEN) * N_SZ + d;
    float pre = Zrow[0], pim = Zrow[1024], gt = Zrow[4096];
    float hre = 0.f, him = 0.f;
    for (int i = 0; i < TLEN; i++) {
        float npre, npim, ngt;
        if (i + 1 < TLEN) {
            const float* nz = Zrow + N_SZ;
            npre = nz[0]; npim = nz[1024]; ngt = nz[4096];
        }
        const float s = 1.f / (1.f + expf(-gt));
        const float ure = s * pre, uim = s * pim;
        const float nre = rre * hre - rim * him + ure;
        him = rre * him + rim * hre + uim;
        hre = nre;
        pre = npre; pim = npim; gt = ngt;
        Zrow += N_SZ;
    }
    g_E[(b * CHUNKS + c) * D_SZ + d] = make_float2(hre, him);
}

__global__ void scan_pass2(const float* __restrict__ omega,
                           const float* __restrict__ lg,
                           const float* __restrict__ dtp) {
    const int d = blockIdx.x * blockDim.x + threadIdx.x;
    const int b = blockIdx.y;
    const float dt = fabsf(*dtp);
    const float decayT = expf(-expf(lg[d]) * dt * (float)TLEN);
    const float angT = omega[d] * dt * (float)TLEN;
    const float rTre = decayT * cosf(angT), rTim = decayT * sinf(angT);

    float cre = 0.f, cim = 0.f;
    for (int c = 0; c < CHUNKS; c++) {
        g_Cy[(b * CHUNKS + c) * D_SZ + d] = make_float2(cre, cim);
        const float2 e = g_E[(b * CHUNKS + c) * D_SZ + d];
        const float nre = e.x + rTre * cre - rTim * cim;
        cim = e.y + rTre * cim + rTim * cre;
        cre = nre;
    }
}

// ---------------------------------------------------------------------------
// Fused scan pass3 + per-row standardization + phi contraction.
// Block = 1024 threads = full D row; per timestep block-reduce sums.
// out = zre*phi_re + zim*phi_im,  z = (h - mean)/(sqrt(var)+1e-6)
// ---------------------------------------------------------------------------
__global__ __launch_bounds__(1024)
void scan3_proj(const float* __restrict__ omega, const float* __restrict__ lg,
                const float* __restrict__ dtp, float* __restrict__ out) {
    const int d = threadIdx.x;
    const int lane = d & 31, warp = d >> 5;
    const int c = blockIdx.x;
    const int b = blockIdx.y;

    __shared__ float sm0[32], sm1[32], sm2[32], sm3[32];
    __shared__ float bc[4];

    const float dt = fabsf(*dtp);
    const float decay = expf(-expf(lg[d]) * dt);
    const float ang = omega[d] * dt;
    const float rre = decay * cosf(ang), rim = decay * sinf(ang);

    const float2 cy = g_Cy[(b * CHUNKS + c) * D_SZ + d];
    float hre = cy.x, him = cy.y;

    const float* Zrow = g_Z + (size_t)(b * L_SZ + c * TLEN) * N_SZ + d;
    float* orow = out + (size_t)(b * L_SZ + c * TLEN) * D_SZ + d;

    float pre = Zrow[0], pim = Zrow[1024], gt = Zrow[4096];
    float phre = Zrow[2048], phim = Zrow[3072];

    const float invD = 1.f / (float)D_SZ;

    for (int i = 0; i < TLEN; i++) {
        float npre, npim, ngt, nphre, nphim;
        if (i + 1 < TLEN) {
            const float* nz = Zrow + N_SZ;
            npre = nz[0]; npim = nz[1024]; ngt = nz[4096];
            nphre = nz[2048]; nphim = nz[3072];
        }
        const float s = 1.f / (1.f + expf(-gt));
        const float ure = s * pre, uim = s * pim;
        const float nre = rre * hre - rim * him + ure;
        him = rre * him + rim * hre + uim;
        hre = nre;

        // block reduce: sum(hre), sum(him), sum(hre^2), sum(him^2)
        float r0 = hre, r1 = him, r2 = hre * hre, r3 = him * him;
#pragma unroll
        for (int off = 16; off > 0; off >>= 1) {
            r0 += __shfl_xor_sync(0xFFFFFFFFu, r0, off);
            r1 += __shfl_xor_sync(0xFFFFFFFFu, r1, off);
            r2 += __shfl_xor_sync(0xFFFFFFFFu, r2, off);
            r3 += __shfl_xor_sync(0xFFFFFFFFu, r3, off);
        }
        if (lane == 0) { sm0[warp] = r0; sm1[warp] = r1; sm2[warp] = r2; sm3[warp] = r3; }
        __syncthreads();
        if (warp == 0) {
            float v0 = sm0[lane], v1 = sm1[lane], v2 = sm2[lane], v3 = sm3[lane];
#pragma unroll
            for (int off = 16; off > 0; off >>= 1) {
                v0 += __shfl_xor_sync(0xFFFFFFFFu, v0, off);
                v1 += __shfl_xor_sync(0xFFFFFFFFu, v1, off);
                v2 += __shfl_xor_sync(0xFFFFFFFFu, v2, off);
                v3 += __shfl_xor_sync(0xFFFFFFFFu, v3, off);
            }
            if (lane == 0) { bc[0] = v0; bc[1] = v1; bc[2] = v2; bc[3] = v3; }
        }
        __syncthreads();
        const float mre = bc[0] * invD, mim = bc[1] * invD;
        const float vre = fmaxf(bc[2] * invD - mre * mre, 0.f);
        const float vim = fmaxf(bc[3] * invD - mim * mim, 0.f);
        const float ivr = 1.f / (sqrtf(vre) + 1e-6f);
        const float ivi = 1.f / (sqrtf(vim) + 1e-6f);

        const float zre = (hre - mre) * ivr;
        const float zim = (him - mim) * ivi;
        *orow = zre * phre + zim * phim;

        pre = npre; pim = npim; gt = ngt; phre = nphre; phim = nphim;
        Zrow += N_SZ;
        orow += D_SZ;
    }
}

// ---------------------------------------------------------------------------
extern "C" void kernel_launch(void* const* d_in, const int* in_sizes, int n_in,
                              void* d_out, int out_size) {
    const float* x     = (const float*)d_in[0];
    const float* omega = (const float*)d_in[1];
    const float* lg    = (const float*)d_in[2];
    const float* dt    = (const float*)d_in[3];
    const float* Wpsi  = (const float*)d_in[4];
    const float* bpsi  = (const float*)d_in[5];
    const float* Wphi  = (const float*)d_in[6];
    const float* bphi  = (const float*)d_in[7];
    const float* Wgate = (const float*)d_in[8];
    const float* bgate = (const float*)d_in[9];
    float* out = (float*)d_out;

    cudaFuncSetAttribute(gemm_tc, cudaFuncAttributeMaxDynamicSharedMemorySize,
                         GEMM_SMEM);

    float* Xa;  cudaGetSymbolAddress((void**)&Xa, g_Xa);
    float* Wc;  cudaGetSymbolAddress((void**)&Wc, g_Wc);
    float* bb;  cudaGetSymbolAddress((void**)&bb, g_bias);

    cvtA_kernel<<<(M_SZ * K_SZ / 4) / 256, 256>>>(x);
    cvtB_kernel<<<(N_SZ * K_SZ / 4) / 256, 256>>>(Wpsi, Wphi, Wgate);
    biascat_kernel<<<N_SZ / 256, 256>>>(bpsi, bphi, bgate);

    gemm_tc<<<dim3(40, 128), 256, GEMM_SMEM>>>(Xa, Wc, bb);

    scan_pass1<<<dim3(CHUNKS, B_SZ), 1024>>>(omega, lg, dt);
    scan_pass2<<<dim3(D_SZ / 256, B_SZ), 256>>>(omega, lg, dt);
    scan3_proj<<<dim3(CHUNKS, B_SZ), 1024>>>(omega, lg, dt, out);
}

// round 7
// speedup vs baseline: 2.9168x; 1.5672x over previous
#include <cuda_runtime.h>
#include <cuda_fp16.h>
#include <math.h>
#include <stdint.h>

// Problem dims
#define B_SZ 4
#define L_SZ 4096
#define D_SZ 1024
#define M_SZ (B_SZ * L_SZ)   // 16384
#define N_SZ (5 * D_SZ)      // 5120
#define K_SZ D_SZ            // 1024

// Scan chunking
#define CHUNKS 32
#define TLEN   128

// Scratch (device globals)
__device__ float  g_Z[(size_t)M_SZ * N_SZ];     // [psi_re|psi_im|phi_re|phi_im|gate]
__device__ float2 g_E[B_SZ * CHUNKS * D_SZ];
__device__ float2 g_Cy[B_SZ * CHUNKS * D_SZ];
__device__ __half g_Xh[(size_t)M_SZ * K_SZ];    // fragment-major fp16 X
__device__ __half g_Wh[(size_t)N_SZ * K_SZ];    // fragment-major fp16 weights
__device__ float  g_bias[N_SZ];

// ---------------------------------------------------------------------------
// helpers
// ---------------------------------------------------------------------------
__device__ __forceinline__ uint32_t smem_u32(const void* p) {
    uint32_t a;
    asm("{ .reg .u64 t; cvta.to.shared.u64 t, %1; cvt.u32.u64 %0, t; }"
        : "=r"(a) : "l"(p));
    return a;
}
__device__ __forceinline__ unsigned pack_h2(float lo, float hi) {
    __half2 h = __floats2half2_rn(lo, hi);
    return *(unsigned*)&h;
}
__device__ __forceinline__ void mma_f16(float c[4], unsigned a0, unsigned a1,
                                        unsigned a2, unsigned a3,
                                        unsigned b0, unsigned b1) {
    asm volatile(
        "mma.sync.aligned.m16n8k16.row.col.f32.f16.f16.f32 "
        "{%0,%1,%2,%3}, {%4,%5,%6,%7}, {%8,%9}, {%0,%1,%2,%3};\n"
        : "+f"(c[0]), "+f"(c[1]), "+f"(c[2]), "+f"(c[3])
        : "r"(a0), "r"(a1), "r"(a2), "r"(a3), "r"(b0), "r"(b1));
}
__device__ __forceinline__ void cp_async16(uint32_t smem, const void* gptr) {
    asm volatile("cp.async.cg.shared.global [%0], [%1], 16;"
                 :: "r"(smem), "l"(gptr) : "memory");
}

// ---------------------------------------------------------------------------
// Fragment-major fp16 pre-convert passes for mma.m16n8k16
//
// A unit u (uint4 = 4 half2 regs): u = ((mb*64 + kt)*8 + mi)*32 + lane
//   m = mb*128 + mi*16 + (lane>>2), k0 = kt*16 + (lane&3)*2
//   reg0 = {X[m,k0],X[m,k0+1]}        reg1 = {X[m+8,k0],X[m+8,k0+1]}
//   reg2 = {X[m,k0+8],X[m,k0+9]}      reg3 = {X[m+8,k0+8],X[m+8,k0+9]}
// ---------------------------------------------------------------------------
__global__ void cvtA_kernel(const float* __restrict__ x) {
    const unsigned u = blockIdx.x * 256 + threadIdx.x;   // < 2097152
    const int lane = u & 31, gid = lane >> 2, tig = lane & 3;
    const int mi = (u >> 5) & 7;
    const int kt = (u >> 8) & 63;
    const int mb = u >> 14;
    const int m = mb * 128 + mi * 16 + gid;
    const int k0 = kt * 16 + tig * 2;
    const float* xp = x + (size_t)m * K_SZ + k0;
    uint4 v;
    v.x = pack_h2(xp[0], xp[1]);
    v.y = pack_h2(xp[8 * K_SZ], xp[8 * K_SZ + 1]);
    v.z = pack_h2(xp[8], xp[9]);
    v.w = pack_h2(xp[8 * K_SZ + 8], xp[8 * K_SZ + 9]);
    ((uint4*)g_Xh)[u] = v;
}

// B unit u (uint2 = 2 half2 regs): u = ((nb*64 + kt)*16 + ni)*32 + lane
//   n = nb*128 + ni*8 + (lane>>2), k0 = kt*16 + (lane&3)*2
//   reg0 = {W[n,k0],W[n,k0+1]}   reg1 = {W[n,k0+8],W[n,k0+9]}
// NOTE: unit count = N_SZ*K_SZ/4 (uint2 = 4 halves) -> 1310720 units
__global__ void cvtB_kernel(const float* __restrict__ Wpsi,
                            const float* __restrict__ Wphi,
                            const float* __restrict__ Wgate) {
    const unsigned u = blockIdx.x * 256 + threadIdx.x;   // < 1310720
    const int lane = u & 31, gid = lane >> 2, tig = lane & 3;
    const int ni = (u >> 5) & 15;
    const int kt = (u >> 9) & 63;
    const int nb = u >> 15;
    const int n = nb * 128 + ni * 8 + gid;
    const int k0 = kt * 16 + tig * 2;
    const float* Wp;
    int n_loc;
    if (n < 2048)      { Wp = Wpsi;  n_loc = n; }
    else if (n < 4096) { Wp = Wphi;  n_loc = n - 2048; }
    else               { Wp = Wgate; n_loc = n - 4096; }
    const float* wp = Wp + (size_t)n_loc * K_SZ + k0;
    uint2 v;
    v.x = pack_h2(wp[0], wp[1]);
    v.y = pack_h2(wp[8], wp[9]);
    ((uint2*)g_Wh)[u] = v;
}

__global__ void biascat_kernel(const float* __restrict__ bp,
                               const float* __restrict__ bh,
                               const float* __restrict__ bg) {
    int i = blockIdx.x * 256 + threadIdx.x;
    float v = (i < 2048) ? bp[i] : ((i < 4096) ? bh[i - 2048] : bg[i - 4096]);
    g_bias[i] = v;
}

// ---------------------------------------------------------------------------
// FP16 mma.sync GEMM, fragment-major smem, 3-stage cp.async pipeline
//   CTA tile 128x128, BK=64 (4 k16 steps/stage), 256 threads
//   8 warps (2M x 4N), warp tile 64x32
//   Stage = A 16KB + B 16KB contiguous
// ---------------------------------------------------------------------------
#define STAGES 3
#define KTILES 16                    // K loop: 16 stages of BK=64
#define STAGE_U4 2048                // uint4 per stage (A 1024 + B 1024)
#define GEMM_SMEM (STAGES * 32768 + 512)

__global__ __launch_bounds__(256, 2)
void gemm_tc(const __half* __restrict__ Xp, const __half* __restrict__ Wp,
             const float* __restrict__ bias) {
    extern __shared__ __align__(16) uint4 smem4[];
    float* bsm = (float*)(smem4 + STAGES * STAGE_U4);

    const int tid = threadIdx.x;
    const int lane = tid & 31, warp = tid >> 5;
    const int warpM = warp & 1, warpN = warp >> 1;
    const int gid = lane >> 2, tig = lane & 3;
    const int bn = blockIdx.x, bm = blockIdx.y;

    if (tid < 128) bsm[tid] = bias[bn * 128 + tid];

    // Global fragment streams: per k64 stage, A & B are each 1024 contiguous uint4
    const uint4* Ag = (const uint4*)Xp + (size_t)bm * 64 * 256;   // 64 kt * 256 u4
    const uint4* Bg = (const uint4*)Wp + (size_t)bn * 64 * 256;
    const uint32_t sb = smem_u32(smem4);

    // prologue: stages 0,1
#pragma unroll
    for (int s = 0; s < STAGES - 1; s++) {
        const uint32_t base = sb + s * 32768;
#pragma unroll
        for (int i = 0; i < 4; i++) {
            const int c = i * 256 + tid;
            cp_async16(base + c * 16, Ag + (size_t)s * 1024 + c);
            cp_async16(base + 16384 + c * 16, Bg + (size_t)s * 1024 + c);
        }
        asm volatile("cp.async.commit_group;" ::: "memory");
    }

    float acc[4][4][4];
#pragma unroll
    for (int i = 0; i < 4; i++)
#pragma unroll
        for (int j = 0; j < 4; j++)
#pragma unroll
            for (int k = 0; k < 4; k++) acc[i][j][k] = 0.f;

    for (int t = 0; t < KTILES; t++) {
        if (t + STAGES - 1 < KTILES) {
            const int tt = t + STAGES - 1;
            const uint32_t base = sb + (tt % STAGES) * 32768;
#pragma unroll
            for (int i = 0; i < 4; i++) {
                const int c = i * 256 + tid;
                cp_async16(base + c * 16, Ag + (size_t)tt * 1024 + c);
                cp_async16(base + 16384 + c * 16, Bg + (size_t)tt * 1024 + c);
            }
        }
        asm volatile("cp.async.commit_group;" ::: "memory");
        asm volatile("cp.async.wait_group %0;" :: "n"(STAGES - 1) : "memory");
        __syncthreads();

        const uint4* As = smem4 + (t % STAGES) * STAGE_U4;
        const uint2* Bs = (const uint2*)(As + 1024);

#pragma unroll
        for (int ktl = 0; ktl < 4; ktl++) {
            uint2 bq[4];
#pragma unroll
            for (int ni = 0; ni < 4; ni++)
                bq[ni] = Bs[(ktl * 16 + warpN * 4 + ni) * 32 + lane];
            uint4 aq[4];
#pragma unroll
            for (int mi = 0; mi < 4; mi++)
                aq[mi] = As[(ktl * 8 + warpM * 4 + mi) * 32 + lane];
#pragma unroll
            for (int mi = 0; mi < 4; mi++)
#pragma unroll
                for (int ni = 0; ni < 4; ni++)
                    mma_f16(acc[mi][ni], aq[mi].x, aq[mi].y, aq[mi].z, aq[mi].w,
                            bq[ni].x, bq[ni].y);
        }
        __syncthreads();
    }

    // Epilogue: bias + store
    const int m0 = bm * 128, n0 = bn * 128;
#pragma unroll
    for (int mi = 0; mi < 4; mi++) {
#pragma unroll
        for (int ni = 0; ni < 4; ni++) {
            const int row = m0 + warpM * 64 + mi * 16 + gid;
            const int colL = warpN * 32 + ni * 8 + tig * 2;
            const float bv0 = bsm[colL];
            const float bv1 = bsm[colL + 1];
            float2 v0 = make_float2(acc[mi][ni][0] + bv0, acc[mi][ni][1] + bv1);
            float2 v1 = make_float2(acc[mi][ni][2] + bv0, acc[mi][ni][3] + bv1);
            *(float2*)&g_Z[(size_t)row * N_SZ + n0 + colL]       = v0;
            *(float2*)&g_Z[(size_t)(row + 8) * N_SZ + n0 + colL] = v1;
        }
    }
}

// ---------------------------------------------------------------------------
// Scan pass1: per-chunk local recurrence ends
// ---------------------------------------------------------------------------
__global__ __launch_bounds__(1024)
void scan_pass1(const float* __restrict__ omega, const float* __restrict__ lg,
                const float* __restrict__ dtp) {
    const int d = threadIdx.x;
    const int c = blockIdx.x;
    const int b = blockIdx.y;
    const float dt = fabsf(*dtp);
    const float decay = expf(-expf(lg[d]) * dt);
    const float ang = omega[d] * dt;
    const float rre = decay * cosf(ang), rim = decay * sinf(ang);

    const float* Zrow = g_Z + (size_t)(b * L_SZ + c * TLEN) * N_SZ + d;
    float pre = Zrow[0], pim = Zrow[1024], gt = Zrow[4096];
    float hre = 0.f, him = 0.f;
    for (int i = 0; i < TLEN; i++) {
        float npre, npim, ngt;
        if (i + 1 < TLEN) {
            const float* nz = Zrow + N_SZ;
            npre = nz[0]; npim = nz[1024]; ngt = nz[4096];
        }
        const float s = 1.f / (1.f + expf(-gt));
        const float ure = s * pre, uim = s * pim;
        const float nre = rre * hre - rim * him + ure;
        him = rre * him + rim * hre + uim;
        hre = nre;
        pre = npre; pim = npim; gt = ngt;
        Zrow += N_SZ;
    }
    g_E[(b * CHUNKS + c) * D_SZ + d] = make_float2(hre, him);
}

__global__ void scan_pass2(const float* __restrict__ omega,
                           const float* __restrict__ lg,
                           const float* __restrict__ dtp) {
    const int d = blockIdx.x * blockDim.x + threadIdx.x;
    const int b = blockIdx.y;
    const float dt = fabsf(*dtp);
    const float decayT = expf(-expf(lg[d]) * dt * (float)TLEN);
    const float angT = omega[d] * dt * (float)TLEN;
    const float rTre = decayT * cosf(angT), rTim = decayT * sinf(angT);

    float cre = 0.f, cim = 0.f;
    for (int c = 0; c < CHUNKS; c++) {
        g_Cy[(b * CHUNKS + c) * D_SZ + d] = make_float2(cre, cim);
        const float2 e = g_E[(b * CHUNKS + c) * D_SZ + d];
        const float nre = e.x + rTre * cre - rTim * cim;
        cim = e.y + rTre * cim + rTim * cre;
        cre = nre;
    }
}

// ---------------------------------------------------------------------------
// Fused scan pass3 + per-row standardization + phi contraction
// ---------------------------------------------------------------------------
__global__ __launch_bounds__(1024)
void scan3_proj(const float* __restrict__ omega, const float* __restrict__ lg,
                const float* __restrict__ dtp, float* __restrict__ out) {
    const int d = threadIdx.x;
    const int lane = d & 31, warp = d >> 5;
    const int c = blockIdx.x;
    const int b = blockIdx.y;

    __shared__ float sm0[32], sm1[32], sm2[32], sm3[32];
    __shared__ float bc[4];

    const float dt = fabsf(*dtp);
    const float decay = expf(-expf(lg[d]) * dt);
    const float ang = omega[d] * dt;
    const float rre = decay * cosf(ang), rim = decay * sinf(ang);

    const float2 cy = g_Cy[(b * CHUNKS + c) * D_SZ + d];
    float hre = cy.x, him = cy.y;

    const float* Zrow = g_Z + (size_t)(b * L_SZ + c * TLEN) * N_SZ + d;
    float* orow = out + (size_t)(b * L_SZ + c * TLEN) * D_SZ + d;

    float pre = Zrow[0], pim = Zrow[1024], gt = Zrow[4096];
    float phre = Zrow[2048], phim = Zrow[3072];

    const float invD = 1.f / (float)D_SZ;

    for (int i = 0; i < TLEN; i++) {
        float npre, npim, ngt, nphre, nphim;
        if (i + 1 < TLEN) {
            const float* nz = Zrow + N_SZ;
            npre = nz[0]; npim = nz[1024]; ngt = nz[4096];
            nphre = nz[2048]; nphim = nz[3072];
        }
        const float s = 1.f / (1.f + expf(-gt));
        const float ure = s * pre, uim = s * pim;
        const float nre = rre * hre - rim * him + ure;
        him = rre * him + rim * hre + uim;
        hre = nre;

        float r0 = hre, r1 = him, r2 = hre * hre, r3 = him * him;
#pragma unroll
        for (int off = 16; off > 0; off >>= 1) {
            r0 += __shfl_xor_sync(0xFFFFFFFFu, r0, off);
            r1 += __shfl_xor_sync(0xFFFFFFFFu, r1, off);
            r2 += __shfl_xor_sync(0xFFFFFFFFu, r2, off);
            r3 += __shfl_xor_sync(0xFFFFFFFFu, r3, off);
        }
        if (lane == 0) { sm0[warp] = r0; sm1[warp] = r1; sm2[warp] = r2; sm3[warp] = r3; }
        __syncthreads();
        if (warp == 0) {
            float v0 = sm0[lane], v1 = sm1[lane], v2 = sm2[lane], v3 = sm3[lane];
#pragma unroll
            for (int off = 16; off > 0; off >>= 1) {
                v0 += __shfl_xor_sync(0xFFFFFFFFu, v0, off);
                v1 += __shfl_xor_sync(0xFFFFFFFFu, v1, off);
                v2 += __shfl_xor_sync(0xFFFFFFFFu, v2, off);
                v3 += __shfl_xor_sync(0xFFFFFFFFu, v3, off);
            }
            if (lane == 0) { bc[0] = v0; bc[1] = v1; bc[2] = v2; bc[3] = v3; }
        }
        __syncthreads();
        const float mre = bc[0] * invD, mim = bc[1] * invD;
        const float vre = fmaxf(bc[2] * invD - mre * mre, 0.f);
        const float vim = fmaxf(bc[3] * invD - mim * mim, 0.f);
        const float ivr = 1.f / (sqrtf(vre) + 1e-6f);
        const float ivi = 1.f / (sqrtf(vim) + 1e-6f);

        const float zre = (hre - mre) * ivr;
        const float zim = (him - mim) * ivi;
        *orow = zre * phre + zim * phim;

        pre = npre; pim = npim; gt = ngt; phre = nphre; phim = nphim;
        Zrow += N_SZ;
        orow += D_SZ;
    }
}

// ---------------------------------------------------------------------------
extern "C" void kernel_launch(void* const* d_in, const int* in_sizes, int n_in,
                              void* d_out, int out_size) {
    const float* x     = (const float*)d_in[0];
    const float* omega = (const float*)d_in[1];
    const float* lg    = (const float*)d_in[2];
    const float* dt    = (const float*)d_in[3];
    const float* Wpsi  = (const float*)d_in[4];
    const float* bpsi  = (const float*)d_in[5];
    const float* Wphi  = (const float*)d_in[6];
    const float* bphi  = (const float*)d_in[7];
    const float* Wgate = (const float*)d_in[8];
    const float* bgate = (const float*)d_in[9];
    float* out = (float*)d_out;

    cudaFuncSetAttribute(gemm_tc, cudaFuncAttributeMaxDynamicSharedMemorySize,
                         GEMM_SMEM);

    __half* Xh;  cudaGetSymbolAddress((void**)&Xh, g_Xh);
    __half* Wh;  cudaGetSymbolAddress((void**)&Wh, g_Wh);
    float* bb;   cudaGetSymbolAddress((void**)&bb, g_bias);

    cvtA_kernel<<<(M_SZ * K_SZ / 8) / 256, 256>>>(x);
    cvtB_kernel<<<(N_SZ * K_SZ / 4) / 256, 256>>>(Wpsi, Wphi, Wgate);   // uint2 units!
    biascat_kernel<<<N_SZ / 256, 256>>>(bpsi, bphi, bgate);

    gemm_tc<<<dim3(40, 128), 256, GEMM_SMEM>>>(Xh, Wh, bb);

    scan_pass1<<<dim3(CHUNKS, B_SZ), 1024>>>(omega, lg, dt);
    scan_pass2<<<dim3(D_SZ / 256, B_SZ), 256>>>(omega, lg, dt);
    scan3_proj<<<dim3(CHUNKS, B_SZ), 1024>>>(omega, lg, dt, out);
}

// round 8
// speedup vs baseline: 3.0346x; 1.0404x over previous
#include <cuda_runtime.h>
#include <cuda_fp16.h>
#include <math.h>
#include <stdint.h>

// Problem dims
#define B_SZ 4
#define L_SZ 4096
#define D_SZ 1024
#define M_SZ (B_SZ * L_SZ)   // 16384
#define N_SZ (5 * D_SZ)      // 5120
#define K_SZ D_SZ            // 1024

// Scan chunking
#define CHUNKS 32
#define TLEN   128
#define GRP    4             // timesteps per batched reduction group

// Scratch (device globals)
__device__ float  g_Z[(size_t)M_SZ * N_SZ];     // [psi_re|psi_im|phi_re|phi_im|gate]
__device__ float2 g_E[B_SZ * CHUNKS * D_SZ];
__device__ float2 g_Cy[B_SZ * CHUNKS * D_SZ];
__device__ __half g_Xh[(size_t)M_SZ * K_SZ];    // fragment-major fp16 X
__device__ __half g_Wh[(size_t)N_SZ * K_SZ];    // fragment-major fp16 weights
__device__ float  g_bias[N_SZ];

// ---------------------------------------------------------------------------
// helpers
// ---------------------------------------------------------------------------
__device__ __forceinline__ uint32_t smem_u32(const void* p) {
    uint32_t a;
    asm("{ .reg .u64 t; cvta.to.shared.u64 t, %1; cvt.u32.u64 %0, t; }"
        : "=r"(a) : "l"(p));
    return a;
}
__device__ __forceinline__ unsigned pack_h2(float lo, float hi) {
    __half2 h = __floats2half2_rn(lo, hi);
    return *(unsigned*)&h;
}
__device__ __forceinline__ void mma_f16(float c[4], unsigned a0, unsigned a1,
                                        unsigned a2, unsigned a3,
                                        unsigned b0, unsigned b1) {
    asm volatile(
        "mma.sync.aligned.m16n8k16.row.col.f32.f16.f16.f32 "
        "{%0,%1,%2,%3}, {%4,%5,%6,%7}, {%8,%9}, {%0,%1,%2,%3};\n"
        : "+f"(c[0]), "+f"(c[1]), "+f"(c[2]), "+f"(c[3])
        : "r"(a0), "r"(a1), "r"(a2), "r"(a3), "r"(b0), "r"(b1));
}
__device__ __forceinline__ void cp_async16(uint32_t smem, const void* gptr) {
    asm volatile("cp.async.cg.shared.global [%0], [%1], 16;"
                 :: "r"(smem), "l"(gptr) : "memory");
}

// ---------------------------------------------------------------------------
// Fragment-major fp16 pre-convert passes (mma.m16n8k16 register layouts)
// ---------------------------------------------------------------------------
__global__ void cvtA_kernel(const float* __restrict__ x) {
    const unsigned u = blockIdx.x * 256 + threadIdx.x;   // < 2097152
    const int lane = u & 31, gid = lane >> 2, tig = lane & 3;
    const int mi = (u >> 5) & 7;
    const int kt = (u >> 8) & 63;
    const int mb = u >> 14;
    const int m = mb * 128 + mi * 16 + gid;
    const int k0 = kt * 16 + tig * 2;
    const float* xp = x + (size_t)m * K_SZ + k0;
    uint4 v;
    v.x = pack_h2(xp[0], xp[1]);
    v.y = pack_h2(xp[8 * K_SZ], xp[8 * K_SZ + 1]);
    v.z = pack_h2(xp[8], xp[9]);
    v.w = pack_h2(xp[8 * K_SZ + 8], xp[8 * K_SZ + 9]);
    ((uint4*)g_Xh)[u] = v;
}

// B unit u (uint2): unit count = N_SZ*K_SZ/4 = 1310720
__global__ void cvtB_kernel(const float* __restrict__ Wpsi,
                            const float* __restrict__ Wphi,
                            const float* __restrict__ Wgate) {
    const unsigned u = blockIdx.x * 256 + threadIdx.x;   // < 1310720
    const int lane = u & 31, gid = lane >> 2, tig = lane & 3;
    const int ni = (u >> 5) & 15;
    const int kt = (u >> 9) & 63;
    const int nb = u >> 15;
    const int n = nb * 128 + ni * 8 + gid;
    const int k0 = kt * 16 + tig * 2;
    const float* Wp;
    int n_loc;
    if (n < 2048)      { Wp = Wpsi;  n_loc = n; }
    else if (n < 4096) { Wp = Wphi;  n_loc = n - 2048; }
    else               { Wp = Wgate; n_loc = n - 4096; }
    const float* wp = Wp + (size_t)n_loc * K_SZ + k0;
    uint2 v;
    v.x = pack_h2(wp[0], wp[1]);
    v.y = pack_h2(wp[8], wp[9]);
    ((uint2*)g_Wh)[u] = v;
}

__global__ void biascat_kernel(const float* __restrict__ bp,
                               const float* __restrict__ bh,
                               const float* __restrict__ bg) {
    int i = blockIdx.x * 256 + threadIdx.x;
    float v = (i < 2048) ? bp[i] : ((i < 4096) ? bh[i - 2048] : bg[i - 4096]);
    g_bias[i] = v;
}

// ---------------------------------------------------------------------------
// FP16 mma.sync GEMM; ONE __syncthreads per K-iteration.
//   Loop: wait_group(1) -> barrier -> issue loads (t+2) -> compute t.
//   WAR-safe: write stage (t+2)%3 == (t-1)%3 was fully read before barrier.
// ---------------------------------------------------------------------------
#define STAGES 3
#define KTILES 16
#define STAGE_U4 2048
#define GEMM_SMEM (STAGES * 32768 + 512)

__global__ __launch_bounds__(256, 2)
void gemm_tc(const __half* __restrict__ Xp, const __half* __restrict__ Wp,
             const float* __restrict__ bias) {
    extern __shared__ __align__(16) uint4 smem4[];
    float* bsm = (float*)(smem4 + STAGES * STAGE_U4);

    const int tid = threadIdx.x;
    const int lane = tid & 31, warp = tid >> 5;
    const int warpM = warp & 1, warpN = warp >> 1;
    const int gid = lane >> 2, tig = lane & 3;
    const int bn = blockIdx.x, bm = blockIdx.y;

    if (tid < 128) bsm[tid] = bias[bn * 128 + tid];

    const uint4* Ag = (const uint4*)Xp + (size_t)bm * 64 * 256;
    const uint4* Bg = (const uint4*)Wp + (size_t)bn * 64 * 256;
    const uint32_t sb = smem_u32(smem4);

    // prologue: stages 0,1
#pragma unroll
    for (int s = 0; s < STAGES - 1; s++) {
        const uint32_t base = sb + s * 32768;
#pragma unroll
        for (int i = 0; i < 4; i++) {
            const int c = i * 256 + tid;
            cp_async16(base + c * 16, Ag + (size_t)s * 1024 + c);
            cp_async16(base + 16384 + c * 16, Bg + (size_t)s * 1024 + c);
        }
        asm volatile("cp.async.commit_group;" ::: "memory");
    }

    float acc[4][4][4];
#pragma unroll
    for (int i = 0; i < 4; i++)
#pragma unroll
        for (int j = 0; j < 4; j++)
#pragma unroll
            for (int k = 0; k < 4; k++) acc[i][j][k] = 0.f;

    for (int t = 0; t < KTILES; t++) {
        asm volatile("cp.async.wait_group 1;" ::: "memory");
        __syncthreads();

        // issue loads for tile t+2 into stage (t+2)%3  (== (t-1)%3, just freed)
        if (t + STAGES - 1 < KTILES) {
            const int tt = t + STAGES - 1;
            const uint32_t base = sb + (tt % STAGES) * 32768;
#pragma unroll
            for (int i = 0; i < 4; i++) {
                const int c = i * 256 + tid;
                cp_async16(base + c * 16, Ag + (size_t)tt * 1024 + c);
                cp_async16(base + 16384 + c * 16, Bg + (size_t)tt * 1024 + c);
            }
        }
        asm volatile("cp.async.commit_group;" ::: "memory");

        const uint4* As = smem4 + (t % STAGES) * STAGE_U4;
        const uint2* Bs = (const uint2*)(As + 1024);

#pragma unroll
        for (int ktl = 0; ktl < 4; ktl++) {
            uint2 bq[4];
#pragma unroll
            for (int ni = 0; ni < 4; ni++)
                bq[ni] = Bs[(ktl * 16 + warpN * 4 + ni) * 32 + lane];
            uint4 aq[4];
#pragma unroll
            for (int mi = 0; mi < 4; mi++)
                aq[mi] = As[(ktl * 8 + warpM * 4 + mi) * 32 + lane];
#pragma unroll
            for (int mi = 0; mi < 4; mi++)
#pragma unroll
                for (int ni = 0; ni < 4; ni++)
                    mma_f16(acc[mi][ni], aq[mi].x, aq[mi].y, aq[mi].z, aq[mi].w,
                            bq[ni].x, bq[ni].y);
        }
    }

    // Epilogue: bias + store
    const int m0 = bm * 128, n0 = bn * 128;
#pragma unroll
    for (int mi = 0; mi < 4; mi++) {
#pragma unroll
        for (int ni = 0; ni < 4; ni++) {
            const int row = m0 + warpM * 64 + mi * 16 + gid;
            const int colL = warpN * 32 + ni * 8 + tig * 2;
            const float bv0 = bsm[colL];
            const float bv1 = bsm[colL + 1];
            float2 v0 = make_float2(acc[mi][ni][0] + bv0, acc[mi][ni][1] + bv1);
            float2 v1 = make_float2(acc[mi][ni][2] + bv0, acc[mi][ni][3] + bv1);
            *(float2*)&g_Z[(size_t)row * N_SZ + n0 + colL]       = v0;
            *(float2*)&g_Z[(size_t)(row + 8) * N_SZ + n0 + colL] = v1;
        }
    }
}

// ---------------------------------------------------------------------------
// Scan pass1: per-chunk local ends; G=4 batched loads for MLP
// ---------------------------------------------------------------------------
__global__ __launch_bounds__(1024)
void scan_pass1(const float* __restrict__ omega, const float* __restrict__ lg,
                const float* __restrict__ dtp) {
    const int d = threadIdx.x;
    const int c = blockIdx.x;
    const int b = blockIdx.y;
    const float dt = fabsf(*dtp);
    const float decay = expf(-expf(lg[d]) * dt);
    const float ang = omega[d] * dt;
    const float rre = decay * cosf(ang), rim = decay * sinf(ang);

    const float* Zrow = g_Z + (size_t)(b * L_SZ + c * TLEN) * N_SZ + d;
    float hre = 0.f, him = 0.f;
    for (int g = 0; g < TLEN / GRP; g++) {
        float Lp[GRP], Li[GRP], Lg[GRP];
#pragma unroll
        for (int i = 0; i < GRP; i++) {
            const float* z = Zrow + (size_t)i * N_SZ;
            Lp[i] = z[0]; Li[i] = z[1024]; Lg[i] = z[4096];
        }
#pragma unroll
        for (int i = 0; i < GRP; i++) {
            const float s = 1.f / (1.f + expf(-Lg[i]));
            const float ure = s * Lp[i], uim = s * Li[i];
            const float nre = rre * hre - rim * him + ure;
            him = rre * him + rim * hre + uim;
            hre = nre;
        }
        Zrow += (size_t)GRP * N_SZ;
    }
    g_E[(b * CHUNKS + c) * D_SZ + d] = make_float2(hre, him);
}

__global__ void scan_pass2(const float* __restrict__ omega,
                           const float* __restrict__ lg,
                           const float* __restrict__ dtp) {
    const int d = blockIdx.x * blockDim.x + threadIdx.x;
    const int b = blockIdx.y;
    const float dt = fabsf(*dtp);
    const float decayT = expf(-expf(lg[d]) * dt * (float)TLEN);
    const float angT = omega[d] * dt * (float)TLEN;
    const float rTre = decayT * cosf(angT), rTim = decayT * sinf(angT);

    float cre = 0.f, cim = 0.f;
    for (int c = 0; c < CHUNKS; c++) {
        g_Cy[(b * CHUNKS + c) * D_SZ + d] = make_float2(cre, cim);
        const float2 e = g_E[(b * CHUNKS + c) * D_SZ + d];
        const float nre = e.x + rTre * cre - rTim * cim;
        cim = e.y + rTre * cim + rTim * cre;
        cre = nre;
    }
}

// ---------------------------------------------------------------------------
// Fused scan pass3 + standardization + phi contraction, G=4 batched:
//   - 20 loads in flight per group
//   - 16 reduction chains (4 steps x 4 sums), 2 barriers per 4 steps
// ---------------------------------------------------------------------------
__global__ __launch_bounds__(1024)
void scan3_proj(const float* __restrict__ omega, const float* __restrict__ lg,
                const float* __restrict__ dtp, float* __restrict__ out) {
    const int d = threadIdx.x;
    const int lane = d & 31, warp = d >> 5;
    const int c = blockIdx.x;
    const int b = blockIdx.y;

    __shared__ float red[16][32];   // [chain][warp]
    __shared__ float bc[16];        // final sums: [step*4 + {sr,si,sr2,si2}]

    const float dt = fabsf(*dtp);
    const float decay = expf(-expf(lg[d]) * dt);
    const float ang = omega[d] * dt;
    const float rre = decay * cosf(ang), rim = decay * sinf(ang);

    const float2 cy = g_Cy[(b * CHUNKS + c) * D_SZ + d];
    float hre = cy.x, him = cy.y;

    const float* Zrow = g_Z + (size_t)(b * L_SZ + c * TLEN) * N_SZ + d;
    float* orow = out + (size_t)(b * L_SZ + c * TLEN) * D_SZ + d;

    const float invD = 1.f / (float)D_SZ;

    for (int g = 0; g < TLEN / GRP; g++) {
        float Lp[GRP], Li[GRP], Lg[GRP], Pr[GRP], Pi[GRP];
#pragma unroll
        for (int i = 0; i < GRP; i++) {
            const float* z = Zrow + (size_t)i * N_SZ;
            Lp[i] = z[0]; Li[i] = z[1024]; Lg[i] = z[4096];
            Pr[i] = z[2048]; Pi[i] = z[3072];
        }

        float hr[GRP], hi[GRP];
#pragma unroll
        for (int i = 0; i < GRP; i++) {
            const float s = 1.f / (1.f + expf(-Lg[i]));
            const float ure = s * Lp[i], uim = s * Li[i];
            const float nre = rre * hre - rim * him + ure;
            him = rre * him + rim * hre + uim;
            hre = nre;
            hr[i] = hre; hi[i] = him;
        }

        // 16 chains: v[i*4+0]=hr, +1=hi, +2=hr^2, +3=hi^2
        float v[16];
#pragma unroll
        for (int i = 0; i < GRP; i++) {
            v[i * 4 + 0] = hr[i];
            v[i * 4 + 1] = hi[i];
            v[i * 4 + 2] = hr[i] * hr[i];
            v[i * 4 + 3] = hi[i] * hi[i];
        }
#pragma unroll
        for (int off = 16; off > 0; off >>= 1)
#pragma unroll
            for (int j = 0; j < 16; j++)
                v[j] += __shfl_xor_sync(0xFFFFFFFFu, v[j], off);
        if (lane == 0)
#pragma unroll
            for (int j = 0; j < 16; j++) red[j][warp] = v[j];
        __syncthreads();

        if (warp < 4) {
            // warp w reduces chains w*4 .. w*4+3 across 32 warps
#pragma unroll
            for (int jj = 0; jj < 4; jj++) {
                const int j = warp * 4 + jj;
                float t = red[j][lane];
#pragma unroll
                for (int off = 16; off > 0; off >>= 1)
                    t += __shfl_xor_sync(0xFFFFFFFFu, t, off);
                if (lane == 0) bc[j] = t;
            }
        }
        __syncthreads();

#pragma unroll
        for (int i = 0; i < GRP; i++) {
            const float mre = bc[i * 4 + 0] * invD;
            const float mim = bc[i * 4 + 1] * invD;
            const float vre = fmaxf(bc[i * 4 + 2] * invD - mre * mre, 0.f);
            const float vim = fmaxf(bc[i * 4 + 3] * invD - mim * mim, 0.f);
            const float ivr = 1.f / (sqrtf(vre) + 1e-6f);
            const float ivi = 1.f / (sqrtf(vim) + 1e-6f);
            const float zre = (hr[i] - mre) * ivr;
            const float zim = (hi[i] - mim) * ivi;
            orow[(size_t)i * D_SZ] = zre * Pr[i] + zim * Pi[i];
        }
        __syncthreads();   // protect red/bc reuse next group

        Zrow += (size_t)GRP * N_SZ;
        orow += (size_t)GRP * D_SZ;
    }
}

// ---------------------------------------------------------------------------
extern "C" void kernel_launch(void* const* d_in, const int* in_sizes, int n_in,
                              void* d_out, int out_size) {
    const float* x     = (const float*)d_in[0];
    const float* omega = (const float*)d_in[1];
    const float* lg    = (const float*)d_in[2];
    const float* dt    = (const float*)d_in[3];
    const float* Wpsi  = (const float*)d_in[4];
    const float* bpsi  = (const float*)d_in[5];
    const float* Wphi  = (const float*)d_in[6];
    const float* bphi  = (const float*)d_in[7];
    const float* Wgate = (const float*)d_in[8];
    const float* bgate = (const float*)d_in[9];
    float* out = (float*)d_out;

    cudaFuncSetAttribute(gemm_tc, cudaFuncAttributeMaxDynamicSharedMemorySize,
                         GEMM_SMEM);

    __half* Xh;  cudaGetSymbolAddress((void**)&Xh, g_Xh);
    __half* Wh;  cudaGetSymbolAddress((void**)&Wh, g_Wh);
    float* bb;   cudaGetSymbolAddress((void**)&bb, g_bias);

    cvtA_kernel<<<(M_SZ * K_SZ / 8) / 256, 256>>>(x);
    cvtB_kernel<<<(N_SZ * K_SZ / 4) / 256, 256>>>(Wpsi, Wphi, Wgate);
    biascat_kernel<<<N_SZ / 256, 256>>>(bpsi, bphi, bgate);

    gemm_tc<<<dim3(40, 128), 256, GEMM_SMEM>>>(Xh, Wh, bb);

    scan_pass1<<<dim3(CHUNKS, B_SZ), 1024>>>(omega, lg, dt);
    scan_pass2<<<dim3(D_SZ / 256, B_SZ), 256>>>(omega, lg, dt);
    scan3_proj<<<dim3(CHUNKS, B_SZ), 1024>>>(omega, lg, dt, out);
}

// round 9
// speedup vs baseline: 3.1630x; 1.0423x over previous
#include <cuda_runtime.h>
#include <cuda_fp16.h>
#include <math.h>
#include <stdint.h>

// Problem dims
#define B_SZ 4
#define L_SZ 4096
#define D_SZ 1024
#define M_SZ (B_SZ * L_SZ)   // 16384
#define N_SZ (5 * D_SZ)      // 5120
#define K_SZ D_SZ            // 1024

// Scan chunking
#define CHUNKS 32
#define TLEN   128
#define GRP    4             // scan3 group
#define GRP1   8             // scan1 group

// Scratch (device globals)
__device__ float  g_Z[(size_t)M_SZ * N_SZ];     // [psi_re|psi_im|phi_re|phi_im|gate]
__device__ float2 g_E[B_SZ * CHUNKS * D_SZ];
__device__ float2 g_Cy[B_SZ * CHUNKS * D_SZ];
__device__ __half g_Xh[(size_t)M_SZ * K_SZ];    // fragment-major fp16 X
__device__ __half g_Wh[(size_t)N_SZ * K_SZ];    // fragment-major fp16 weights
__device__ float  g_bias[N_SZ];

// ---------------------------------------------------------------------------
// helpers
// ---------------------------------------------------------------------------
__device__ __forceinline__ uint32_t smem_u32(const void* p) {
    uint32_t a;
    asm("{ .reg .u64 t; cvta.to.shared.u64 t, %1; cvt.u32.u64 %0, t; }"
        : "=r"(a) : "l"(p));
    return a;
}
__device__ __forceinline__ unsigned pack_h2(float lo, float hi) {
    __half2 h = __floats2half2_rn(lo, hi);
    return *(unsigned*)&h;
}
__device__ __forceinline__ void mma_f16(float c[4], unsigned a0, unsigned a1,
                                        unsigned a2, unsigned a3,
                                        unsigned b0, unsigned b1) {
    asm volatile(
        "mma.sync.aligned.m16n8k16.row.col.f32.f16.f16.f32 "
        "{%0,%1,%2,%3}, {%4,%5,%6,%7}, {%8,%9}, {%0,%1,%2,%3};\n"
        : "+f"(c[0]), "+f"(c[1]), "+f"(c[2]), "+f"(c[3])
        : "r"(a0), "r"(a1), "r"(a2), "r"(a3), "r"(b0), "r"(b1));
}
__device__ __forceinline__ void cp_async16(uint32_t smem, const void* gptr) {
    asm volatile("cp.async.cg.shared.global [%0], [%1], 16;"
                 :: "r"(smem), "l"(gptr) : "memory");
}

// ---------------------------------------------------------------------------
// Fragment-major fp16 pre-convert passes (mma.m16n8k16 register layouts)
// ---------------------------------------------------------------------------
__global__ void cvtA_kernel(const float* __restrict__ x) {
    const unsigned u = blockIdx.x * 256 + threadIdx.x;   // < 2097152
    const int lane = u & 31, gid = lane >> 2, tig = lane & 3;
    const int mi = (u >> 5) & 7;
    const int kt = (u >> 8) & 63;
    const int mb = u >> 14;
    const int m = mb * 128 + mi * 16 + gid;
    const int k0 = kt * 16 + tig * 2;
    const float* xp = x + (size_t)m * K_SZ + k0;
    uint4 v;
    v.x = pack_h2(xp[0], xp[1]);
    v.y = pack_h2(xp[8 * K_SZ], xp[8 * K_SZ + 1]);
    v.z = pack_h2(xp[8], xp[9]);
    v.w = pack_h2(xp[8 * K_SZ + 8], xp[8 * K_SZ + 9]);
    ((uint4*)g_Xh)[u] = v;
}

// B unit u (uint2): unit count = N_SZ*K_SZ/4 = 1310720
__global__ void cvtB_kernel(const float* __restrict__ Wpsi,
                            const float* __restrict__ Wphi,
                            const float* __restrict__ Wgate) {
    const unsigned u = blockIdx.x * 256 + threadIdx.x;   // < 1310720
    const int lane = u & 31, gid = lane >> 2, tig = lane & 3;
    const int ni = (u >> 5) & 15;
    const int kt = (u >> 9) & 63;
    const int nb = u >> 15;
    const int n = nb * 128 + ni * 8 + gid;
    const int k0 = kt * 16 + tig * 2;
    const float* Wp;
    int n_loc;
    if (n < 2048)      { Wp = Wpsi;  n_loc = n; }
    else if (n < 4096) { Wp = Wphi;  n_loc = n - 2048; }
    else               { Wp = Wgate; n_loc = n - 4096; }
    const float* wp = Wp + (size_t)n_loc * K_SZ + k0;
    uint2 v;
    v.x = pack_h2(wp[0], wp[1]);
    v.y = pack_h2(wp[8], wp[9]);
    ((uint2*)g_Wh)[u] = v;
}

__global__ void biascat_kernel(const float* __restrict__ bp,
                               const float* __restrict__ bh,
                               const float* __restrict__ bg) {
    int i = blockIdx.x * 256 + threadIdx.x;
    float v = (i < 2048) ? bp[i] : ((i < 4096) ? bh[i - 2048] : bg[i - 4096]);
    g_bias[i] = v;
}

// ---------------------------------------------------------------------------
// FP16 mma.sync GEMM: 128 threads, 4 warps (2M x 2N), warp tile 64x64.
//   CTA tile 128x128, BK=64, 3-stage cp.async, one barrier per K-iter.
//   A and B each read only 2x from smem (was A 4x) -> 0.75x smem traffic.
// ---------------------------------------------------------------------------
#define STAGES 3
#define KTILES 16
#define STAGE_U4 2048
#define GEMM_SMEM (STAGES * 32768 + 512)

__global__ __launch_bounds__(128, 2)
void gemm_tc(const __half* __restrict__ Xp, const __half* __restrict__ Wp,
             const float* __restrict__ bias) {
    extern __shared__ __align__(16) uint4 smem4[];
    float* bsm = (float*)(smem4 + STAGES * STAGE_U4);

    const int tid = threadIdx.x;                 // 0..127
    const int lane = tid & 31, warp = tid >> 5;  // warp 0..3
    const int warpM = warp & 1, warpN = warp >> 1;
    const int gid = lane >> 2, tig = lane & 3;
    const int bn = blockIdx.x, bm = blockIdx.y;

    bsm[tid] = bias[bn * 128 + tid];

    const uint4* Ag = (const uint4*)Xp + (size_t)bm * 64 * 256;
    const uint4* Bg = (const uint4*)Wp + (size_t)bn * 64 * 256;
    const uint32_t sb = smem_u32(smem4);

    // prologue: stages 0,1 (each thread: 8 A + 8 B cp.async)
#pragma unroll
    for (int s = 0; s < STAGES - 1; s++) {
        const uint32_t base = sb + s * 32768;
#pragma unroll
        for (int i = 0; i < 8; i++) {
            const int c = i * 128 + tid;
            cp_async16(base + c * 16, Ag + (size_t)s * 1024 + c);
            cp_async16(base + 16384 + c * 16, Bg + (size_t)s * 1024 + c);
        }
        asm volatile("cp.async.commit_group;" ::: "memory");
    }

    float acc[4][8][4];
#pragma unroll
    for (int i = 0; i < 4; i++)
#pragma unroll
        for (int j = 0; j < 8; j++)
#pragma unroll
            for (int k = 0; k < 4; k++) acc[i][j][k] = 0.f;

    for (int t = 0; t < KTILES; t++) {
        asm volatile("cp.async.wait_group 1;" ::: "memory");
        __syncthreads();

        // issue loads for tile t+2 into just-freed stage
        if (t + STAGES - 1 < KTILES) {
            const int tt = t + STAGES - 1;
            const uint32_t base = sb + (tt % STAGES) * 32768;
#pragma unroll
            for (int i = 0; i < 8; i++) {
                const int c = i * 128 + tid;
                cp_async16(base + c * 16, Ag + (size_t)tt * 1024 + c);
                cp_async16(base + 16384 + c * 16, Bg + (size_t)tt * 1024 + c);
            }
        }
        asm volatile("cp.async.commit_group;" ::: "memory");

        const uint4* As = smem4 + (t % STAGES) * STAGE_U4;
        const uint2* Bs = (const uint2*)(As + 1024);

#pragma unroll
        for (int ktl = 0; ktl < 4; ktl++) {
            uint2 bq[8];
#pragma unroll
            for (int ni = 0; ni < 8; ni++)
                bq[ni] = Bs[(ktl * 16 + warpN * 8 + ni) * 32 + lane];
            uint4 aq[4];
#pragma unroll
            for (int mi = 0; mi < 4; mi++)
                aq[mi] = As[(ktl * 8 + warpM * 4 + mi) * 32 + lane];
#pragma unroll
            for (int mi = 0; mi < 4; mi++)
#pragma unroll
                for (int ni = 0; ni < 8; ni++)
                    mma_f16(acc[mi][ni], aq[mi].x, aq[mi].y, aq[mi].z, aq[mi].w,
                            bq[ni].x, bq[ni].y);
        }
    }

    // Epilogue: bias + store (warp tile 64x64)
    const int m0 = bm * 128, n0 = bn * 128;
#pragma unroll
    for (int mi = 0; mi < 4; mi++) {
#pragma unroll
        for (int ni = 0; ni < 8; ni++) {
            const int row = m0 + warpM * 64 + mi * 16 + gid;
            const int colL = warpN * 64 + ni * 8 + tig * 2;
            const float bv0 = bsm[colL];
            const float bv1 = bsm[colL + 1];
            float2 v0 = make_float2(acc[mi][ni][0] + bv0, acc[mi][ni][1] + bv1);
            float2 v1 = make_float2(acc[mi][ni][2] + bv0, acc[mi][ni][3] + bv1);
            *(float2*)&g_Z[(size_t)row * N_SZ + n0 + colL]       = v0;
            *(float2*)&g_Z[(size_t)(row + 8) * N_SZ + n0 + colL] = v1;
        }
    }
}

// ---------------------------------------------------------------------------
// Scan pass1: per-chunk local ends; G=8 batched loads for MLP
// ---------------------------------------------------------------------------
__global__ __launch_bounds__(1024)
void scan_pass1(const float* __restrict__ omega, const float* __restrict__ lg,
                const float* __restrict__ dtp) {
    const int d = threadIdx.x;
    const int c = blockIdx.x;
    const int b = blockIdx.y;
    const float dt = fabsf(*dtp);
    const float decay = expf(-expf(lg[d]) * dt);
    const float ang = omega[d] * dt;
    const float rre = decay * cosf(ang), rim = decay * sinf(ang);

    const float* Zrow = g_Z + (size_t)(b * L_SZ + c * TLEN) * N_SZ + d;
    float hre = 0.f, him = 0.f;
    for (int g = 0; g < TLEN / GRP1; g++) {
        float Lp[GRP1], Li[GRP1], Lg[GRP1];
#pragma unroll
        for (int i = 0; i < GRP1; i++) {
            const float* z = Zrow + (size_t)i * N_SZ;
            Lp[i] = z[0]; Li[i] = z[1024]; Lg[i] = z[4096];
        }
#pragma unroll
        for (int i = 0; i < GRP1; i++) {
            const float s = 1.f / (1.f + expf(-Lg[i]));
            const float ure = s * Lp[i], uim = s * Li[i];
            const float nre = rre * hre - rim * him + ure;
            him = rre * him + rim * hre + uim;
            hre = nre;
        }
        Zrow += (size_t)GRP1 * N_SZ;
    }
    g_E[(b * CHUNKS + c) * D_SZ + d] = make_float2(hre, him);
}

__global__ void scan_pass2(const float* __restrict__ omega,
                           const float* __restrict__ lg,
                           const float* __restrict__ dtp) {
    const int d = blockIdx.x * blockDim.x + threadIdx.x;
    const int b = blockIdx.y;
    const float dt = fabsf(*dtp);
    const float decayT = expf(-expf(lg[d]) * dt * (float)TLEN);
    const float angT = omega[d] * dt * (float)TLEN;
    const float rTre = decayT * cosf(angT), rTim = decayT * sinf(angT);

    float cre = 0.f, cim = 0.f;
    for (int c = 0; c < CHUNKS; c++) {
        g_Cy[(b * CHUNKS + c) * D_SZ + d] = make_float2(cre, cim);
        const float2 e = g_E[(b * CHUNKS + c) * D_SZ + d];
        const float nre = e.x + rTre * cre - rTim * cim;
        cim = e.y + rTre * cim + rTim * cre;
        cre = nre;
    }
}

// ---------------------------------------------------------------------------
// Fused scan pass3 + standardization + phi contraction, G=4 batched
// ---------------------------------------------------------------------------
__global__ __launch_bounds__(1024)
void scan3_proj(const float* __restrict__ omega, const float* __restrict__ lg,
                const float* __restrict__ dtp, float* __restrict__ out) {
    const int d = threadIdx.x;
    const int lane = d & 31, warp = d >> 5;
    const int c = blockIdx.x;
    const int b = blockIdx.y;

    __shared__ float red[16][32];
    __shared__ float bc[16];

    const float dt = fabsf(*dtp);
    const float decay = expf(-expf(lg[d]) * dt);
    const float ang = omega[d] * dt;
    const float rre = decay * cosf(ang), rim = decay * sinf(ang);

    const float2 cy = g_Cy[(b * CHUNKS + c) * D_SZ + d];
    float hre = cy.x, him = cy.y;

    const float* Zrow = g_Z + (size_t)(b * L_SZ + c * TLEN) * N_SZ + d;
    float* orow = out + (size_t)(b * L_SZ + c * TLEN) * D_SZ + d;

    const float invD = 1.f / (float)D_SZ;

    for (int g = 0; g < TLEN / GRP; g++) {
        float Lp[GRP], Li[GRP], Lg[GRP], Pr[GRP], Pi[GRP];
#pragma unroll
        for (int i = 0; i < GRP; i++) {
            const float* z = Zrow + (size_t)i * N_SZ;
            Lp[i] = z[0]; Li[i] = z[1024]; Lg[i] = z[4096];
            Pr[i] = z[2048]; Pi[i] = z[3072];
        }

        float hr[GRP], hi[GRP];
#pragma unroll
        for (int i = 0; i < GRP; i++) {
            const float s = 1.f / (1.f + expf(-Lg[i]));
            const float ure = s * Lp[i], uim = s * Li[i];
            const float nre = rre * hre - rim * him + ure;
            him = rre * him + rim * hre + uim;
            hre = nre;
            hr[i] = hre; hi[i] = him;
        }

        float v[16];
#pragma unroll
        for (int i = 0; i < GRP; i++) {
            v[i * 4 + 0] = hr[i];
            v[i * 4 + 1] = hi[i];
            v[i * 4 + 2] = hr[i] * hr[i];
            v[i * 4 + 3] = hi[i] * hi[i];
        }
#pragma unroll
        for (int off = 16; off > 0; off >>= 1)
#pragma unroll
            for (int j = 0; j < 16; j++)
                v[j] += __shfl_xor_sync(0xFFFFFFFFu, v[j], off);
        if (lane == 0)
#pragma unroll
            for (int j = 0; j < 16; j++) red[j][warp] = v[j];
        __syncthreads();

        if (warp < 4) {
#pragma unroll
            for (int jj = 0; jj < 4; jj++) {
                const int j = warp * 4 + jj;
                float t = red[j][lane];
#pragma unroll
                for (int off = 16; off > 0; off >>= 1)
                    t += __shfl_xor_sync(0xFFFFFFFFu, t, off);
                if (lane == 0) bc[j] = t;
            }
        }
        __syncthreads();

#pragma unroll
        for (int i = 0; i < GRP; i++) {
            const float mre = bc[i * 4 + 0] * invD;
            const float mim = bc[i * 4 + 1] * invD;
            const float vre = fmaxf(bc[i * 4 + 2] * invD - mre * mre, 0.f);
            const float vim = fmaxf(bc[i * 4 + 3] * invD - mim * mim, 0.f);
            const float ivr = 1.f / (sqrtf(vre) + 1e-6f);
            const float ivi = 1.f / (sqrtf(vim) + 1e-6f);
            const float zre = (hr[i] - mre) * ivr;
            const float zim = (hi[i] - mim) * ivi;
            orow[(size_t)i * D_SZ] = zre * Pr[i] + zim * Pi[i];
        }
        __syncthreads();

        Zrow += (size_t)GRP * N_SZ;
        orow += (size_t)GRP * D_SZ;
    }
}

// ---------------------------------------------------------------------------
extern "C" void kernel_launch(void* const* d_in, const int* in_sizes, int n_in,
                              void* d_out, int out_size) {
    const float* x     = (const float*)d_in[0];
    const float* omega = (const float*)d_in[1];
    const float* lg    = (const float*)d_in[2];
    const float* dt    = (const float*)d_in[3];
    const float* Wpsi  = (const float*)d_in[4];
    const float* bpsi  = (const float*)d_in[5];
    const float* Wphi  = (const float*)d_in[6];
    const float* bphi  = (const float*)d_in[7];
    const float* Wgate = (const float*)d_in[8];
    const float* bgate = (const float*)d_in[9];
    float* out = (float*)d_out;

    cudaFuncSetAttribute(gemm_tc, cudaFuncAttributeMaxDynamicSharedMemorySize,
                         GEMM_SMEM);

    __half* Xh;  cudaGetSymbolAddress((void**)&Xh, g_Xh);
    __half* Wh;  cudaGetSymbolAddress((void**)&Wh, g_Wh);
    float* bb;   cudaGetSymbolAddress((void**)&bb, g_bias);

    cvtA_kernel<<<(M_SZ * K_SZ / 8) / 256, 256>>>(x);
    cvtB_kernel<<<(N_SZ * K_SZ / 4) / 256, 256>>>(Wpsi, Wphi, Wgate);
    biascat_kernel<<<N_SZ / 256, 256>>>(bpsi, bphi, bgate);

    gemm_tc<<<dim3(40, 128), 128, GEMM_SMEM>>>(Xh, Wh, bb);

    scan_pass1<<<dim3(CHUNKS, B_SZ), 1024>>>(omega, lg, dt);
    scan_pass2<<<dim3(D_SZ / 256, B_SZ), 256>>>(omega, lg, dt);
    scan3_proj<<<dim3(CHUNKS, B_SZ), 1024>>>(omega, lg, dt, out);
}